// round 1
// baseline (speedup 1.0000x reference)
#include <cuda_runtime.h>
#include <math.h>

// ---------------------------------------------------------------------------
// Shapes (fixed for this problem)
//   B=2, H=W=256, C=128, S=16  -> G=256 groups, N=256 patches
//   CI=64, F1=384, HF=192, R = 2 branches * B * G = 1024
// ---------------------------------------------------------------------------
#define R_TOT   1024
#define NPATCH  256
#define CI_DIM  64
#define HF_DIM  192
#define F1_DIM  384

// Scratch (device globals; allocation in kernel_launch is forbidden)
__device__ float g_bufin[R_TOT * NPATCH * CI_DIM];   // blocked gmlp input (both branches)
__device__ float g_upre [R_TOT * NPATCH * HF_DIM];   // u pre-ln3; later reused as gate buf [R][HF][N]
__device__ float g_v    [R_TOT * NPATCH * HF_DIM];   // v
__device__ float g_ut   [R_TOT * HF_DIM * NPATCH];   // u^T after ln3; later reused as uv [R][N][HF]
__device__ float g_z    [R_TOT * NPATCH * CI_DIM];   // gmlp output (incl. inner residual)

__device__ __forceinline__ float gelu_exact(float x) {
    return 0.5f * x * (1.0f + erff(x * 0.7071067811865476f));
}

// ---------------------------------------------------------------------------
// K1: ln1 + Dense(W_proj) + GELU, scatter into blocked layout for both branches
// grid 8192 x 256 thr; 16 pixels per block
// ---------------------------------------------------------------------------
__global__ __launch_bounds__(256) void k1_ln_proj(
    const float* __restrict__ x, const float* __restrict__ ln1g,
    const float* __restrict__ ln1b, const float* __restrict__ Wp,
    const float* __restrict__ bp)
{
    __shared__ float sR[16][132];
    __shared__ float sg[128], sb[128];
    __shared__ float smean[16], srs[16];
    const int t = threadIdx.x;
    const int pbase = blockIdx.x * 16;

    if (t < 128) { sg[t] = ln1g[t]; sb[t] = ln1b[t]; }
    const float* xblk = x + (size_t)pbase * 128;
#pragma unroll
    for (int it = 0; it < 8; ++it) {
        int lin = t + it * 256;
        sR[lin >> 7][lin & 127] = xblk[lin];
    }
    __syncthreads();

    const int warp = t >> 5, lane = t & 31;
#pragma unroll
    for (int rr = 0; rr < 2; ++rr) {
        int p = warp * 2 + rr;
        float s = 0.f, s2 = 0.f;
#pragma unroll
        for (int j = 0; j < 4; ++j) {
            float v = sR[p][lane + j * 32];
            s += v; s2 += v * v;
        }
#pragma unroll
        for (int off = 16; off > 0; off >>= 1) {
            s  += __shfl_xor_sync(0xffffffffu, s,  off);
            s2 += __shfl_xor_sync(0xffffffffu, s2, off);
        }
        if (lane == 0) {
            float m = s * (1.f / 128.f);
            float var = s2 * (1.f / 128.f) - m * m;
            smean[p] = m;
            srs[p]   = rsqrtf(var + 1e-3f);
        }
    }
    __syncthreads();
#pragma unroll
    for (int it = 0; it < 8; ++it) {
        int lin = t + it * 256;
        int p = lin >> 7, c = lin & 127;
        sR[p][c] = (sR[p][c] - smean[p]) * srs[p] * sg[c] + sb[c];
    }
    __syncthreads();

    // GEMM: 16 pixels x 128 out-ch, thread = (2 out-ch, 4 pixels)
    const int f2 = t & 63;         // out-ch pair index -> f = 2*f2, 2*f2+1
    const int pg = t >> 6;         // pixel group 0..3 (4 pixels each)
    float acc0[4], acc1[4];
#pragma unroll
    for (int i = 0; i < 4; ++i) { acc0[i] = 0.f; acc1[i] = 0.f; }
    const float2* Wp2 = (const float2*)Wp;
    for (int cc = 0; cc < 128; cc += 4) {
        float4 a0 = *(const float4*)&sR[pg * 4 + 0][cc];
        float4 a1 = *(const float4*)&sR[pg * 4 + 1][cc];
        float4 a2 = *(const float4*)&sR[pg * 4 + 2][cc];
        float4 a3 = *(const float4*)&sR[pg * 4 + 3][cc];
        float2 w0 = Wp2[(cc + 0) * 64 + f2];
        float2 w1 = Wp2[(cc + 1) * 64 + f2];
        float2 w2 = Wp2[(cc + 2) * 64 + f2];
        float2 w3 = Wp2[(cc + 3) * 64 + f2];
        float4 av[4] = {a0, a1, a2, a3};
#pragma unroll
        for (int i = 0; i < 4; ++i) {
            acc0[i] = fmaf(av[i].x, w0.x, acc0[i]); acc1[i] = fmaf(av[i].x, w0.y, acc1[i]);
            acc0[i] = fmaf(av[i].y, w1.x, acc0[i]); acc1[i] = fmaf(av[i].y, w1.y, acc1[i]);
            acc0[i] = fmaf(av[i].z, w2.x, acc0[i]); acc1[i] = fmaf(av[i].z, w2.y, acc1[i]);
            acc0[i] = fmaf(av[i].w, w3.x, acc0[i]); acc1[i] = fmaf(av[i].w, w3.y, acc1[i]);
        }
    }
    const float2 wb = ((const float2*)bp)[f2];
    const int branch = (f2 >= 32) ? 1 : 0;
    const int cloc = 2 * (f2 & 31);
#pragma unroll
    for (int i = 0; i < 4; ++i) {
        int p = pbase + pg * 4 + i;
        int b = p >> 16, h = (p >> 8) & 255, w = p & 255;
        int g  = ((h >> 4) << 4) | (w >> 4);       // block group
        int nn = ((h & 15) << 4) | (w & 15);       // patch in block
        float v0 = gelu_exact(acc0[i] + wb.x);
        float v1 = gelu_exact(acc1[i] + wb.y);
        int r = branch * 512 + (b << 8) + g;
        *(float2*)&g_bufin[(((r << 8) + nn) << 6) + cloc] = make_float2(v0, v1);
    }
}

// ---------------------------------------------------------------------------
// K2: ln2 + per-patch einsum y = gelu(lnx @ W1[n] + b1[n]); split into u_pre/v
// grid (6 f-tiles, 16 r-tiles, 256 n) x 256 thr. BM=64, BN=64, K=64 (full).
// ---------------------------------------------------------------------------
__global__ __launch_bounds__(256) void k2_gmlp_in(
    const float* __restrict__ W1, const float* __restrict__ b1_,
    const float* __restrict__ ln2g, const float* __restrict__ ln2b)
{
    __shared__ float As[64][68];   // A^T: [c][row]
    __shared__ float Bs[64][68];   // W1 tile: [c][f]
    __shared__ float sg[64], sb[64];
    const int t = threadIdx.x;
    const int ftile = blockIdx.x;
    const int rbase = blockIdx.y * 64;
    const int n = blockIdx.z;

    if (t < 64) { sg[t] = ln2g[t]; sb[t] = ln2b[t]; }
    {   // load A transposed
        int c = t & 63, i0 = t >> 6;
#pragma unroll
        for (int it = 0; it < 16; ++it) {
            int i = i0 + it * 4;
            As[c][i] = g_bufin[(((rbase + i) << 8) + n) * 64 + c];
        }
    }
    {   // load W1 tile
        int f = t & 63, c0 = t >> 6;
        const float* W1n = W1 + (size_t)n * 64 * 384 + ftile * 64;
#pragma unroll
        for (int it = 0; it < 16; ++it) {
            int c = c0 + it * 4;
            Bs[c][f] = W1n[c * 384 + f];
        }
    }
    __syncthreads();
    if (t < 64) {   // ln2 per row (column t of As)
        float s = 0.f, s2 = 0.f;
#pragma unroll
        for (int c = 0; c < 64; ++c) { float v = As[c][t]; s += v; s2 += v * v; }
        float m  = s * (1.f / 64.f);
        float rs = rsqrtf(s2 * (1.f / 64.f) - m * m + 1e-3f);
#pragma unroll
        for (int c = 0; c < 64; ++c)
            As[c][t] = (As[c][t] - m) * rs * sg[c] + sb[c];
    }
    __syncthreads();

    const int f0 = (t & 15) * 4;
    const int m0 = (t >> 4) * 4;
    float acc[4][4] = {};
#pragma unroll 8
    for (int c = 0; c < 64; ++c) {
        float4 av = *(const float4*)&As[c][m0];
        float4 bv = *(const float4*)&Bs[c][f0];
        float ar[4] = {av.x, av.y, av.z, av.w};
        float br[4] = {bv.x, bv.y, bv.z, bv.w};
#pragma unroll
        for (int i = 0; i < 4; ++i)
#pragma unroll
            for (int j = 0; j < 4; ++j)
                acc[i][j] = fmaf(ar[i], br[j], acc[i][j]);
    }

    const float4 bias = *(const float4*)&b1_[n * 384 + ftile * 64 + f0];
    float* dst = (ftile < 3) ? g_upre : g_v;
    const int fo = ((ftile < 3) ? ftile : (ftile - 3)) * 64 + f0;
#pragma unroll
    for (int mi = 0; mi < 4; ++mi) {
        int row = rbase + m0 + mi;
        float4 o;
        o.x = gelu_exact(acc[mi][0] + bias.x);
        o.y = gelu_exact(acc[mi][1] + bias.y);
        o.z = gelu_exact(acc[mi][2] + bias.z);
        o.w = gelu_exact(acc[mi][3] + bias.w);
        *(float4*)&dst[((row << 8) + n) * 192 + fo] = o;
    }
}

// ---------------------------------------------------------------------------
// K2b: ln3 over u (HF=192) + transpose -> g_ut[r][c][n]
// grid (1024 r, 8 n-tiles) x 256 thr
// ---------------------------------------------------------------------------
__global__ __launch_bounds__(256) void k2b_ln3_t(
    const float* __restrict__ ln3g, const float* __restrict__ ln3b)
{
    __shared__ float s[32][193];
    __shared__ float sm[32], sr[32];
    const int t = threadIdx.x;
    const int r = blockIdx.x;
    const int nb = blockIdx.y * 32;
    const float* src = g_upre + (((size_t)r << 8) + nb) * 192;
#pragma unroll
    for (int it = 0; it < 24; ++it) {
        int lin = t + it * 256;
        s[lin / 192][lin % 192] = src[lin];
    }
    __syncthreads();
    const int warp = t >> 5, lane = t & 31;
#pragma unroll
    for (int j = 0; j < 4; ++j) {
        int row = warp * 4 + j;
        float su = 0.f, s2 = 0.f;
#pragma unroll
        for (int k = 0; k < 6; ++k) { float v = s[row][lane + k * 32]; su += v; s2 += v * v; }
#pragma unroll
        for (int off = 16; off > 0; off >>= 1) {
            su += __shfl_xor_sync(0xffffffffu, su, off);
            s2 += __shfl_xor_sync(0xffffffffu, s2, off);
        }
        if (lane == 0) {
            float m = su * (1.f / 192.f);
            sm[row] = m;
            sr[row] = rsqrtf(s2 * (1.f / 192.f) - m * m + 1e-3f);
        }
    }
    __syncthreads();
    const int n_l = t & 31, c0 = t >> 5;
#pragma unroll
    for (int it = 0; it < 24; ++it) {
        int c = c0 + it * 8;
        float v = (s[n_l][c] - sm[n_l]) * sr[n_l] * ln3g[c] + ln3b[c];
        g_ut[((r * 192 + c) << 8) + nb + n_l] = v;
    }
}

// ---------------------------------------------------------------------------
// K3: spatial gating. Per-channel c: gate[r][m] = sum_n ut[r][c][n]*Wsgu[c][n][m] + bsgu[c][m]
// grid (4 m-tiles, 16 r-tiles, 192 c) x 256 thr. BM=64(r), BN=64(m), BK=32.
// Output into g_upre reinterpreted as [R][HF][N].
// ---------------------------------------------------------------------------
__global__ __launch_bounds__(256) void k3_sgu(
    const float* __restrict__ Wsgu, const float* __restrict__ bsgu)
{
    __shared__ float As[32][68];   // [k][row]
    __shared__ float Bs[32][68];   // [k][m]
    const int t = threadIdx.x;
    const int mbase = blockIdx.x * 64;
    const int rbase = blockIdx.y * 64;
    const int c = blockIdx.z;
    const int f0 = (t & 15) * 4;   // m
    const int r0 = (t >> 4) * 4;   // row
    float acc[4][4] = {};

    for (int kb = 0; kb < 256; kb += 32) {
        {
            int k = t & 31, i0 = t >> 5;
#pragma unroll
            for (int it = 0; it < 8; ++it) {
                int i = i0 + it * 8;
                As[k][i] = g_ut[(((rbase + i) * 192 + c) << 8) + kb + k];
            }
        }
        {
            int m = t & 63, k0 = t >> 6;
#pragma unroll
            for (int it = 0; it < 8; ++it) {
                int k = k0 + it * 4;
                Bs[k][m] = Wsgu[(((c << 8) + kb + k) << 8) + mbase + m];
            }
        }
        __syncthreads();
#pragma unroll
        for (int k = 0; k < 32; ++k) {
            float4 av = *(const float4*)&As[k][r0];
            float4 bv = *(const float4*)&Bs[k][f0];
            float ar[4] = {av.x, av.y, av.z, av.w};
            float br[4] = {bv.x, bv.y, bv.z, bv.w};
#pragma unroll
            for (int i = 0; i < 4; ++i)
#pragma unroll
                for (int j = 0; j < 4; ++j)
                    acc[i][j] = fmaf(ar[i], br[j], acc[i][j]);
        }
        __syncthreads();
    }
    const float4 bg = *(const float4*)&bsgu[(c << 8) + mbase + f0];
#pragma unroll
    for (int ri = 0; ri < 4; ++ri) {
        float4 o = make_float4(acc[ri][0] + bg.x, acc[ri][1] + bg.y,
                               acc[ri][2] + bg.z, acc[ri][3] + bg.w);
        *(float4*)&g_upre[(((rbase + r0 + ri) * 192 + c) << 8) + mbase + f0] = o;
    }
}

// ---------------------------------------------------------------------------
// K3b: uv[r][n][c] = gate[r][c][n] * v[r][n][c]  (transpose-multiply)
// grid (1024 r, 8 n-tiles, 6 c-tiles) x 256. Output into g_ut as [R][N][HF].
// ---------------------------------------------------------------------------
__global__ __launch_bounds__(256) void k3b_gate_mul()
{
    __shared__ float s[32][33];
    const int t = threadIdx.x;
    const int r = blockIdx.x;
    const int nb = blockIdx.y * 32;
    const int cb = blockIdx.z * 32;
    {
        int n_l = t & 31, c0 = t >> 5;
#pragma unroll
        for (int it = 0; it < 4; ++it) {
            int cc = c0 + it * 8;
            s[cc][n_l] = g_upre[((r * 192 + cb + cc) << 8) + nb + n_l];
        }
    }
    __syncthreads();
    {
        int c_l = t & 31, n0 = t >> 5;
#pragma unroll
        for (int it = 0; it < 4; ++it) {
            int nn = n0 + it * 8;
            int idx = (((r << 8) + nb + nn) * 192) + cb + c_l;
            g_ut[idx] = s[c_l][nn] * g_v[idx];
        }
    }
}

// ---------------------------------------------------------------------------
// K4: z = uv @ W2[n] + b2[n] + bufin (inner residual)
// grid (16 r-tiles, 256 n) x 256 thr. BM=64, BN=64(full CI), BK=32.
// ---------------------------------------------------------------------------
__global__ __launch_bounds__(256) void k4_gmlp_out(
    const float* __restrict__ W2, const float* __restrict__ b2_)
{
    __shared__ float As[32][68];   // [c][row]
    __shared__ float Bs[32][68];   // [c][f]
    const int t = threadIdx.x;
    const int rbase = blockIdx.x * 64;
    const int n = blockIdx.y;
    const int f0 = (t & 15) * 4;
    const int r0 = (t >> 4) * 4;
    float acc[4][4] = {};

    for (int cb = 0; cb < 192; cb += 32) {
        {
            int cl = t & 31, i0 = t >> 5;
#pragma unroll
            for (int it = 0; it < 8; ++it) {
                int i = i0 + it * 8;
                As[cl][i] = g_ut[((((rbase + i) << 8) + n) * 192) + cb + cl];
            }
        }
        {
            int f = t & 63, c0 = t >> 6;
#pragma unroll
            for (int it = 0; it < 8; ++it) {
                int cidx = c0 + it * 4;
                Bs[cidx][f] = W2[((size_t)n * 192 + cb + cidx) * 64 + f];
            }
        }
        __syncthreads();
#pragma unroll
        for (int k = 0; k < 32; ++k) {
            float4 av = *(const float4*)&As[k][r0];
            float4 bv = *(const float4*)&Bs[k][f0];
            float ar[4] = {av.x, av.y, av.z, av.w};
            float br[4] = {bv.x, bv.y, bv.z, bv.w};
#pragma unroll
            for (int i = 0; i < 4; ++i)
#pragma unroll
                for (int j = 0; j < 4; ++j)
                    acc[i][j] = fmaf(ar[i], br[j], acc[i][j]);
        }
        __syncthreads();
    }
    const float4 bias = *(const float4*)&b2_[(n << 6) + f0];
#pragma unroll
    for (int ri = 0; ri < 4; ++ri) {
        int row = rbase + r0 + ri;
        int idx = (((row << 8) + n) << 6) + f0;
        float4 xin = *(const float4*)&g_bufin[idx];
        float4 o = make_float4(acc[ri][0] + bias.x + xin.x,
                               acc[ri][1] + bias.y + xin.y,
                               acc[ri][2] + bias.z + xin.z,
                               acc[ri][3] + bias.w + xin.w);
        *(float4*)&g_z[idx] = o;
    }
}

// ---------------------------------------------------------------------------
// K5: recon_grids(local) / recon_blocks(glob) + concat + outer residual; glob out
// grid 8192 x 256 thr; 16 pixels per block, float4 per thread
// ---------------------------------------------------------------------------
__global__ __launch_bounds__(256) void k5_assemble(
    const float* __restrict__ x, float* __restrict__ out,
    float* __restrict__ gout, int write_glob)
{
    const int t = threadIdx.x;
    const int pix = blockIdx.x * 16 + (t >> 4);
    const int c = (t & 15) * 4;
    const int b = pix >> 16, h = (pix >> 8) & 255, w = pix & 255;
    const int gb  = ((h >> 4) << 4) | (w >> 4);     // block group of pixel
    const int nb2 = ((h & 15) << 4) | (w & 15);     // patch within block
    // local branch read: recon_grids -> gmlp[b, g=nb2, n=gb]
    const int rl = (b << 8) + nb2;
    // glob branch read: recon_blocks -> gmlp[b, g=gb, n=nb2]
    const int rg = 512 + (b << 8) + gb;
    float4 zl = *(const float4*)&g_z[(((rl << 8) + gb)  << 6) + c];
    float4 zg = *(const float4*)&g_z[(((rg << 8) + nb2) << 6) + c];
    float4 xa = *(const float4*)&x[pix * 128 + c];
    float4 xb = *(const float4*)&x[pix * 128 + 64 + c];
    *(float4*)&out[pix * 128 + c] =
        make_float4(zl.x + xa.x, zl.y + xa.y, zl.z + xa.z, zl.w + xa.w);
    *(float4*)&out[pix * 128 + 64 + c] =
        make_float4(zg.x + xb.x, zg.y + xb.y, zg.z + xb.z, zg.w + xb.w);
    if (write_glob)
        *(float4*)&gout[pix * 64 + c] = zg;
}

// ---------------------------------------------------------------------------
extern "C" void kernel_launch(void* const* d_in, const int* in_sizes, int n_in,
                              void* d_out, int out_size)
{
    const float* x    = (const float*)d_in[0];
    const float* ln1g = (const float*)d_in[1];
    const float* ln1b = (const float*)d_in[2];
    const float* Wp   = (const float*)d_in[3];
    const float* bp   = (const float*)d_in[4];
    const float* ln2g = (const float*)d_in[5];
    const float* ln2b = (const float*)d_in[6];
    const float* W1   = (const float*)d_in[7];
    const float* b1   = (const float*)d_in[8];
    const float* ln3g = (const float*)d_in[9];
    const float* ln3b = (const float*)d_in[10];
    const float* Wsgu = (const float*)d_in[11];
    const float* bsgu = (const float*)d_in[12];
    const float* W2   = (const float*)d_in[13];
    const float* b2   = (const float*)d_in[14];

    float* out = (float*)d_out;
    const int OUT_MAIN = 2 * 256 * 256 * 128;   // 16,777,216
    const int OUT_GLOB = 2 * 256 * 256 * 64;    //  8,388,608
    int write_glob = (out_size >= OUT_MAIN + OUT_GLOB) ? 1 : 0;
    float* gout = out + OUT_MAIN;

    k1_ln_proj   <<<8192, 256>>>(x, ln1g, ln1b, Wp, bp);
    k2_gmlp_in   <<<dim3(6, 16, 256), 256>>>(W1, b1, ln2g, ln2b);
    k2b_ln3_t    <<<dim3(1024, 8, 1), 256>>>(ln3g, ln3b);
    k3_sgu       <<<dim3(4, 16, 192), 256>>>(Wsgu, bsgu);
    k3b_gate_mul <<<dim3(1024, 8, 6), 256>>>();
    k4_gmlp_out  <<<dim3(16, 256, 1), 256>>>(W2, b2);
    k5_assemble  <<<8192, 256>>>(x, out, gout, write_glob);
}

// round 3
// speedup vs baseline: 1.2221x; 1.2221x over previous
#include <cuda_runtime.h>
#include <math.h>

// ---------------------------------------------------------------------------
// Shapes: B=2, H=W=256, C=128, S=16 -> G=256, N=256, CI=64, F1=384, HF=192
// R = 2 branches * B * G = 1024
// ---------------------------------------------------------------------------
#define R_TOT   1024
#define NPATCH  256
#define CI_DIM  64
#define HF_DIM  192

__device__ float g_bufin[R_TOT * NPATCH * CI_DIM];   // blocked gmlp input
__device__ float g_upre [R_TOT * NPATCH * HF_DIM];   // u pre-ln3; reused as gate [R][HF][N]
__device__ float g_v    [R_TOT * NPATCH * HF_DIM];   // v
__device__ float g_ut   [R_TOT * HF_DIM * NPATCH];   // u^T ln3'd; reused as uv [R][N][HF]
__device__ float g_z    [R_TOT * NPATCH * CI_DIM];   // gmlp output

__device__ __forceinline__ float gelu_exact(float x) {
    return 0.5f * x * (1.0f + erff(x * 0.7071067811865476f));
}

// ---------------------------------------------------------------------------
// K1: ln1 + Dense(W_proj) + GELU, scatter into blocked layout
// ---------------------------------------------------------------------------
__global__ __launch_bounds__(256) void k1_ln_proj(
    const float* __restrict__ x, const float* __restrict__ ln1g,
    const float* __restrict__ ln1b, const float* __restrict__ Wp,
    const float* __restrict__ bp)
{
    __shared__ float sR[16][132];
    __shared__ float sg[128], sb[128];
    __shared__ float smean[16], srs[16];
    const int t = threadIdx.x;
    const int pbase = blockIdx.x * 16;

    if (t < 128) { sg[t] = ln1g[t]; sb[t] = ln1b[t]; }
    const float* xblk = x + (size_t)pbase * 128;
#pragma unroll
    for (int it = 0; it < 8; ++it) {
        int lin = t + it * 256;
        sR[lin >> 7][lin & 127] = xblk[lin];
    }
    __syncthreads();

    const int warp = t >> 5, lane = t & 31;
#pragma unroll
    for (int rr = 0; rr < 2; ++rr) {
        int p = warp * 2 + rr;
        float s = 0.f, s2 = 0.f;
#pragma unroll
        for (int j = 0; j < 4; ++j) {
            float v = sR[p][lane + j * 32];
            s += v; s2 += v * v;
        }
#pragma unroll
        for (int off = 16; off > 0; off >>= 1) {
            s  += __shfl_xor_sync(0xffffffffu, s,  off);
            s2 += __shfl_xor_sync(0xffffffffu, s2, off);
        }
        if (lane == 0) {
            float m = s * (1.f / 128.f);
            smean[p] = m;
            srs[p]   = rsqrtf(s2 * (1.f / 128.f) - m * m + 1e-3f);
        }
    }
    __syncthreads();
#pragma unroll
    for (int it = 0; it < 8; ++it) {
        int lin = t + it * 256;
        int p = lin >> 7, c = lin & 127;
        sR[p][c] = (sR[p][c] - smean[p]) * srs[p] * sg[c] + sb[c];
    }
    __syncthreads();

    const int f2 = t & 63;
    const int pg = t >> 6;
    float acc0[4], acc1[4];
#pragma unroll
    for (int i = 0; i < 4; ++i) { acc0[i] = 0.f; acc1[i] = 0.f; }
    const float2* Wp2 = (const float2*)Wp;
    for (int cc = 0; cc < 128; cc += 4) {
        float4 a0 = *(const float4*)&sR[pg * 4 + 0][cc];
        float4 a1 = *(const float4*)&sR[pg * 4 + 1][cc];
        float4 a2 = *(const float4*)&sR[pg * 4 + 2][cc];
        float4 a3 = *(const float4*)&sR[pg * 4 + 3][cc];
        float2 w0 = Wp2[(cc + 0) * 64 + f2];
        float2 w1 = Wp2[(cc + 1) * 64 + f2];
        float2 w2 = Wp2[(cc + 2) * 64 + f2];
        float2 w3 = Wp2[(cc + 3) * 64 + f2];
        float4 av[4] = {a0, a1, a2, a3};
#pragma unroll
        for (int i = 0; i < 4; ++i) {
            acc0[i] = fmaf(av[i].x, w0.x, acc0[i]); acc1[i] = fmaf(av[i].x, w0.y, acc1[i]);
            acc0[i] = fmaf(av[i].y, w1.x, acc0[i]); acc1[i] = fmaf(av[i].y, w1.y, acc1[i]);
            acc0[i] = fmaf(av[i].z, w2.x, acc0[i]); acc1[i] = fmaf(av[i].z, w2.y, acc1[i]);
            acc0[i] = fmaf(av[i].w, w3.x, acc0[i]); acc1[i] = fmaf(av[i].w, w3.y, acc1[i]);
        }
    }
    const float2 wb = ((const float2*)bp)[f2];
    const int branch = (f2 >= 32) ? 1 : 0;
    const int cloc = 2 * (f2 & 31);
#pragma unroll
    for (int i = 0; i < 4; ++i) {
        int p = pbase + pg * 4 + i;
        int b = p >> 16, h = (p >> 8) & 255, w = p & 255;
        int g  = ((h >> 4) << 4) | (w >> 4);
        int nn = ((h & 15) << 4) | (w & 15);
        float v0 = gelu_exact(acc0[i] + wb.x);
        float v1 = gelu_exact(acc1[i] + wb.y);
        int r = branch * 512 + (b << 8) + g;
        *(float2*)&g_bufin[(((r << 8) + nn) << 6) + cloc] = make_float2(v0, v1);
    }
}

// ---------------------------------------------------------------------------
// K2: ln2 + y = gelu(lnx @ W1[n] + b1[n]); split -> u_pre / v
// 128(rows) x 128(f) tile, 8x8/thread, K=64 (A resident, ln2 from registers)
// grid (3 ftiles, 8 rtiles, 256 n) x 256
// ---------------------------------------------------------------------------
__global__ __launch_bounds__(256) void k2_gmlp_in(
    const float* __restrict__ W1, const float* __restrict__ b1_,
    const float* __restrict__ ln2g, const float* __restrict__ ln2b)
{
    __shared__ float As[64][132];   // [k][row]
    __shared__ float Bs[16][132];   // [k][f]
    __shared__ float sg[64], sb[64];
    const int t = threadIdx.x;
    const int fbase = blockIdx.x * 128;
    const int rbase = blockIdx.y * 128;
    const int n = blockIdx.z;

    if (t < 64) { sg[t] = ln2g[t]; sb[t] = ln2b[t]; }

    // ---- A load + ln2 (2 threads per row) ----
    {
        const int row = t >> 1, bsel = t & 1;
        const float* src = g_bufin + ((size_t)((rbase + row) << 8) + n) * 64;
        float4 va[8];
        float s = 0.f, s2 = 0.f;
#pragma unroll
        for (int j = 0; j < 8; ++j) {
            va[j] = *(const float4*)&src[bsel * 4 + j * 8];
            s  += va[j].x + va[j].y + va[j].z + va[j].w;
            s2 += va[j].x * va[j].x + va[j].y * va[j].y
                + va[j].z * va[j].z + va[j].w * va[j].w;
        }
        s  += __shfl_xor_sync(0xffffffffu, s,  1);
        s2 += __shfl_xor_sync(0xffffffffu, s2, 1);
        float m  = s * (1.f / 64.f);
        float rs = rsqrtf(s2 * (1.f / 64.f) - m * m + 1e-3f);
        __syncthreads();  // sg/sb ready
#pragma unroll
        for (int j = 0; j < 8; ++j) {
            int k = bsel * 4 + j * 8;
            As[k + 0][row] = (va[j].x - m) * rs * sg[k + 0] + sb[k + 0];
            As[k + 1][row] = (va[j].y - m) * rs * sg[k + 1] + sb[k + 1];
            As[k + 2][row] = (va[j].z - m) * rs * sg[k + 2] + sb[k + 2];
            As[k + 3][row] = (va[j].w - m) * rs * sg[k + 3] + sb[k + 3];
        }
    }

    const int tx = t & 15, ty = t >> 4;
    const int m0 = tx * 4, r0 = ty * 4;
    float acc[8][8] = {};

    const int bm4 = (t & 31) * 4, bk0 = t >> 5;   // B loader mapping
    const float* Wn = W1 + (size_t)n * 64 * 384 + fbase;

    for (int kb = 0; kb < 4; ++kb) {
        __syncthreads();
        *(float4*)&Bs[bk0    ][bm4] = *(const float4*)&Wn[(kb * 16 + bk0    ) * 384 + bm4];
        *(float4*)&Bs[bk0 + 8][bm4] = *(const float4*)&Wn[(kb * 16 + bk0 + 8) * 384 + bm4];
        __syncthreads();
#pragma unroll
        for (int kk = 0; kk < 16; ++kk) {
            int k = kb * 16 + kk;
            float4 a0 = *(const float4*)&As[k][r0];
            float4 a1 = *(const float4*)&As[k][r0 + 64];
            float4 b0 = *(const float4*)&Bs[kk][m0];
            float4 b1 = *(const float4*)&Bs[kk][m0 + 64];
            float ar[8] = {a0.x, a0.y, a0.z, a0.w, a1.x, a1.y, a1.z, a1.w};
            float br[8] = {b0.x, b0.y, b0.z, b0.w, b1.x, b1.y, b1.z, b1.w};
#pragma unroll
            for (int i = 0; i < 8; ++i)
#pragma unroll
                for (int j = 0; j < 8; ++j)
                    acc[i][j] = fmaf(ar[i], br[j], acc[i][j]);
        }
    }

    // ---- epilogue: bias + gelu, route split 192 ----
#pragma unroll
    for (int jg = 0; jg < 2; ++jg) {
        int fg = fbase + m0 + jg * 64;           // global f of this float4 group
        float4 bias = *(const float4*)&b1_[n * 384 + fg];
        float* dst; int fo;
        if (fg < 192) { dst = g_upre; fo = fg; }
        else          { dst = g_v;    fo = fg - 192; }
#pragma unroll
        for (int i = 0; i < 8; ++i) {
            int row = rbase + (i < 4 ? r0 + i : 64 + r0 + i - 4);
            float4 o;
            o.x = gelu_exact(acc[i][jg * 4 + 0] + bias.x);
            o.y = gelu_exact(acc[i][jg * 4 + 1] + bias.y);
            o.z = gelu_exact(acc[i][jg * 4 + 2] + bias.z);
            o.w = gelu_exact(acc[i][jg * 4 + 3] + bias.w);
            *(float4*)&dst[((row << 8) + n) * 192 + fo] = o;
        }
    }
}

// ---------------------------------------------------------------------------
// K2b: ln3 over u (HF=192) + transpose -> g_ut[r][c][n]
// ---------------------------------------------------------------------------
__global__ __launch_bounds__(256) void k2b_ln3_t(
    const float* __restrict__ ln3g, const float* __restrict__ ln3b)
{
    __shared__ float s[32][193];
    __shared__ float sm[32], sr[32];
    const int t = threadIdx.x;
    const int r = blockIdx.x;
    const int nb = blockIdx.y * 32;
    const float* src = g_upre + (((size_t)r << 8) + nb) * 192;
#pragma unroll
    for (int it = 0; it < 24; ++it) {
        int lin = t + it * 256;
        s[lin / 192][lin % 192] = src[lin];
    }
    __syncthreads();
    const int warp = t >> 5, lane = t & 31;
#pragma unroll
    for (int j = 0; j < 4; ++j) {
        int row = warp * 4 + j;
        float su = 0.f, s2 = 0.f;
#pragma unroll
        for (int k = 0; k < 6; ++k) { float v = s[row][lane + k * 32]; su += v; s2 += v * v; }
#pragma unroll
        for (int off = 16; off > 0; off >>= 1) {
            su += __shfl_xor_sync(0xffffffffu, su, off);
            s2 += __shfl_xor_sync(0xffffffffu, s2, off);
        }
        if (lane == 0) {
            float m = su * (1.f / 192.f);
            sm[row] = m;
            sr[row] = rsqrtf(s2 * (1.f / 192.f) - m * m + 1e-3f);
        }
    }
    __syncthreads();
    const int n_l = t & 31, c0 = t >> 5;
#pragma unroll
    for (int it = 0; it < 24; ++it) {
        int c = c0 + it * 8;
        float v = (s[n_l][c] - sm[n_l]) * sr[n_l] * ln3g[c] + ln3b[c];
        g_ut[((r * 192 + c) << 8) + nb + n_l] = v;
    }
}

// ---------------------------------------------------------------------------
// K3: spatial gating GEMM per channel c:
//   gate[r][m] = sum_n ut[r][c][n] * Wsgu[c][n][m] + bsgu[c][m]
// 128(rows) x 128(m) tile, 8x8/thread, BK=16
// grid (2 mtiles, 8 rtiles, 192 c) x 256. Output -> g_upre as [R][HF][N].
// ---------------------------------------------------------------------------
__global__ __launch_bounds__(256) void k3_sgu(
    const float* __restrict__ Wsgu, const float* __restrict__ bsgu)
{
    __shared__ float As[16][132];   // [k][row]
    __shared__ float Bs[16][132];   // [k][m]
    const int t = threadIdx.x;
    const int mbase = blockIdx.x * 128;
    const int rbase = blockIdx.y * 128;
    const int c = blockIdx.z;

    const int tx = t & 15, ty = t >> 4;
    const int m0 = tx * 4, r0 = ty * 4;
    float acc[8][8] = {};

    const int a_row = t >> 1, a_b = t & 1;
    const float* a_src = g_ut + ((size_t)(rbase + a_row) * 192 + c) * 256;
    const int bm4 = (t & 31) * 4, bk0 = t >> 5;
    const float* b_src = Wsgu + ((size_t)c << 16) + mbase;

    for (int kb = 0; kb < 256; kb += 16) {
        float4 v0 = *(const float4*)&a_src[kb + a_b * 4];
        float4 v1 = *(const float4*)&a_src[kb + a_b * 4 + 8];
        float4 w0 = *(const float4*)&b_src[(size_t)(kb + bk0    ) * 256 + bm4];
        float4 w1 = *(const float4*)&b_src[(size_t)(kb + bk0 + 8) * 256 + bm4];
        __syncthreads();
        {
            int k0 = a_b * 4;
            As[k0 + 0][a_row] = v0.x; As[k0 + 1][a_row] = v0.y;
            As[k0 + 2][a_row] = v0.z; As[k0 + 3][a_row] = v0.w;
            As[k0 + 8][a_row] = v1.x; As[k0 + 9][a_row] = v1.y;
            As[k0 +10][a_row] = v1.z; As[k0 +11][a_row] = v1.w;
            *(float4*)&Bs[bk0    ][bm4] = w0;
            *(float4*)&Bs[bk0 + 8][bm4] = w1;
        }
        __syncthreads();
#pragma unroll
        for (int k = 0; k < 16; ++k) {
            float4 a0 = *(const float4*)&As[k][r0];
            float4 a1 = *(const float4*)&As[k][r0 + 64];
            float4 b0 = *(const float4*)&Bs[k][m0];
            float4 b1 = *(const float4*)&Bs[k][m0 + 64];
            float ar[8] = {a0.x, a0.y, a0.z, a0.w, a1.x, a1.y, a1.z, a1.w};
            float br[8] = {b0.x, b0.y, b0.z, b0.w, b1.x, b1.y, b1.z, b1.w};
#pragma unroll
            for (int i = 0; i < 8; ++i)
#pragma unroll
                for (int j = 0; j < 8; ++j)
                    acc[i][j] = fmaf(ar[i], br[j], acc[i][j]);
        }
    }

    float4 bg0 = *(const float4*)&bsgu[(c << 8) + mbase + m0];
    float4 bg1 = *(const float4*)&bsgu[(c << 8) + mbase + m0 + 64];
#pragma unroll
    for (int i = 0; i < 8; ++i) {
        int row = rbase + (i < 4 ? r0 + i : 64 + r0 + i - 4);
        float* dst = &g_upre[((size_t)(row * 192 + c) << 8) + mbase];
        *(float4*)&dst[m0] = make_float4(acc[i][0] + bg0.x, acc[i][1] + bg0.y,
                                         acc[i][2] + bg0.z, acc[i][3] + bg0.w);
        *(float4*)&dst[m0 + 64] = make_float4(acc[i][4] + bg1.x, acc[i][5] + bg1.y,
                                              acc[i][6] + bg1.z, acc[i][7] + bg1.w);
    }
}

// ---------------------------------------------------------------------------
// K3b: uv[r][n][c] = gate[r][c][n] * v[r][n][c]
// ---------------------------------------------------------------------------
__global__ __launch_bounds__(256) void k3b_gate_mul()
{
    __shared__ float s[32][33];
    const int t = threadIdx.x;
    const int r = blockIdx.x;
    const int nb = blockIdx.y * 32;
    const int cb = blockIdx.z * 32;
    {
        int n_l = t & 31, c0 = t >> 5;
#pragma unroll
        for (int it = 0; it < 4; ++it) {
            int cc = c0 + it * 8;
            s[cc][n_l] = g_upre[((r * 192 + cb + cc) << 8) + nb + n_l];
        }
    }
    __syncthreads();
    {
        int c_l = t & 31, n0 = t >> 5;
#pragma unroll
        for (int it = 0; it < 4; ++it) {
            int nn = n0 + it * 8;
            int idx = (((r << 8) + nb + nn) * 192) + cb + c_l;
            g_ut[idx] = s[c_l][nn] * g_v[idx];
        }
    }
}

// ---------------------------------------------------------------------------
// K4: z = uv @ W2[n] + b2[n] + bufin
// 128(rows) x 64(f) tile, 8x4/thread, BK=16; grid (8 rtiles, 256 n) x 256
// ---------------------------------------------------------------------------
__global__ __launch_bounds__(256) void k4_gmlp_out(
    const float* __restrict__ W2, const float* __restrict__ b2_)
{
    __shared__ float As[16][132];
    __shared__ float Bs[16][68];
    const int t = threadIdx.x;
    const int rbase = blockIdx.x * 128;
    const int n = blockIdx.y;

    const int tx = t & 15, ty = t >> 4;
    const int f0 = tx * 4, r0 = ty * 4;
    float acc[8][4] = {};

    const int a_row = t >> 1, a_b = t & 1;
    const float* a_src = g_ut + ((size_t)((rbase + a_row) << 8) + n) * 192;
    const int bf4 = (t & 15) * 4, bk = t >> 4;
    const float* b_src = W2 + (size_t)n * 192 * 64;

    for (int kb = 0; kb < 192; kb += 16) {
        float4 v0 = *(const float4*)&a_src[kb + a_b * 4];
        float4 v1 = *(const float4*)&a_src[kb + a_b * 4 + 8];
        float4 w0 = *(const float4*)&b_src[(kb + bk) * 64 + bf4];
        __syncthreads();
        {
            int k0 = a_b * 4;
            As[k0 + 0][a_row] = v0.x; As[k0 + 1][a_row] = v0.y;
            As[k0 + 2][a_row] = v0.z; As[k0 + 3][a_row] = v0.w;
            As[k0 + 8][a_row] = v1.x; As[k0 + 9][a_row] = v1.y;
            As[k0 +10][a_row] = v1.z; As[k0 +11][a_row] = v1.w;
            *(float4*)&Bs[bk][bf4] = w0;
        }
        __syncthreads();
#pragma unroll
        for (int k = 0; k < 16; ++k) {
            float4 a0 = *(const float4*)&As[k][r0];
            float4 a1 = *(const float4*)&As[k][r0 + 64];
            float4 b0 = *(const float4*)&Bs[k][f0];
            float ar[8] = {a0.x, a0.y, a0.z, a0.w, a1.x, a1.y, a1.z, a1.w};
            float br[4] = {b0.x, b0.y, b0.z, b0.w};
#pragma unroll
            for (int i = 0; i < 8; ++i)
#pragma unroll
                for (int j = 0; j < 4; ++j)
                    acc[i][j] = fmaf(ar[i], br[j], acc[i][j]);
        }
    }

    float4 bias = *(const float4*)&b2_[(n << 6) + f0];
#pragma unroll
    for (int i = 0; i < 8; ++i) {
        int row = rbase + (i < 4 ? r0 + i : 64 + r0 + i - 4);
        int idx = (((row << 8) + n) << 6) + f0;
        float4 xin = *(const float4*)&g_bufin[idx];
        *(float4*)&g_z[idx] = make_float4(acc[i][0] + bias.x + xin.x,
                                          acc[i][1] + bias.y + xin.y,
                                          acc[i][2] + bias.z + xin.z,
                                          acc[i][3] + bias.w + xin.w);
    }
}

// ---------------------------------------------------------------------------
// K5: recon + concat + outer residual; glob out
// ---------------------------------------------------------------------------
__global__ __launch_bounds__(256) void k5_assemble(
    const float* __restrict__ x, float* __restrict__ out,
    float* __restrict__ gout, int write_glob)
{
    const int t = threadIdx.x;
    const int pix = blockIdx.x * 16 + (t >> 4);
    const int c = (t & 15) * 4;
    const int b = pix >> 16, h = (pix >> 8) & 255, w = pix & 255;
    const int gb  = ((h >> 4) << 4) | (w >> 4);
    const int nb2 = ((h & 15) << 4) | (w & 15);
    const int rl = (b << 8) + nb2;
    const int rg = 512 + (b << 8) + gb;
    float4 zl = *(const float4*)&g_z[(((rl << 8) + gb)  << 6) + c];
    float4 zg = *(const float4*)&g_z[(((rg << 8) + nb2) << 6) + c];
    float4 xa = *(const float4*)&x[pix * 128 + c];
    float4 xb = *(const float4*)&x[pix * 128 + 64 + c];
    *(float4*)&out[pix * 128 + c] =
        make_float4(zl.x + xa.x, zl.y + xa.y, zl.z + xa.z, zl.w + xa.w);
    *(float4*)&out[pix * 128 + 64 + c] =
        make_float4(zg.x + xb.x, zg.y + xb.y, zg.z + xb.z, zg.w + xb.w);
    if (write_glob)
        *(float4*)&gout[pix * 64 + c] = zg;
}

// ---------------------------------------------------------------------------
extern "C" void kernel_launch(void* const* d_in, const int* in_sizes, int n_in,
                              void* d_out, int out_size)
{
    const float* x    = (const float*)d_in[0];
    const float* ln1g = (const float*)d_in[1];
    const float* ln1b = (const float*)d_in[2];
    const float* Wp   = (const float*)d_in[3];
    const float* bp   = (const float*)d_in[4];
    const float* ln2g = (const float*)d_in[5];
    const float* ln2b = (const float*)d_in[6];
    const float* W1   = (const float*)d_in[7];
    const float* b1   = (const float*)d_in[8];
    const float* ln3g = (const float*)d_in[9];
    const float* ln3b = (const float*)d_in[10];
    const float* Wsgu = (const float*)d_in[11];
    const float* bsgu = (const float*)d_in[12];
    const float* W2   = (const float*)d_in[13];
    const float* b2   = (const float*)d_in[14];

    float* out = (float*)d_out;
    const int OUT_MAIN = 2 * 256 * 256 * 128;
    const int OUT_GLOB = 2 * 256 * 256 * 64;
    int write_glob = (out_size >= OUT_MAIN + OUT_GLOB) ? 1 : 0;
    float* gout = out + OUT_MAIN;

    k1_ln_proj   <<<8192, 256>>>(x, ln1g, ln1b, Wp, bp);
    k2_gmlp_in   <<<dim3(3, 8, 256), 256>>>(W1, b1, ln2g, ln2b);
    k2b_ln3_t    <<<dim3(1024, 8, 1), 256>>>(ln3g, ln3b);
    k3_sgu       <<<dim3(2, 8, 192), 256>>>(Wsgu, bsgu);
    k3b_gate_mul <<<dim3(1024, 8, 6), 256>>>();
    k4_gmlp_out  <<<dim3(8, 256, 1), 256>>>(W2, b2);
    k5_assemble  <<<8192, 256>>>(x, out, gout, write_glob);
}

// round 4
// speedup vs baseline: 1.2553x; 1.0271x over previous
#include <cuda_runtime.h>
#include <math.h>

// ---------------------------------------------------------------------------
// Shapes: B=2, H=W=256, C=128, S=16 -> G=256, N=256, CI=64, F1=384, HF=192
// R = 2 branches * B * G = 1024
// ---------------------------------------------------------------------------
#define R_TOT   1024
#define NPATCH  256
#define CI_DIM  64
#define HF_DIM  192

__device__ float g_bufin[R_TOT * NPATCH * CI_DIM];   // blocked gmlp input
__device__ float g_upre [R_TOT * NPATCH * HF_DIM];   // u pre-ln3; reused as gate [R][HF][N]
__device__ float g_v    [R_TOT * NPATCH * HF_DIM];   // v
__device__ float g_ut   [R_TOT * HF_DIM * NPATCH];   // u^T ln3'd; reused as uv [R][N][HF]
__device__ float g_z    [R_TOT * NPATCH * CI_DIM];   // gmlp output

__device__ __forceinline__ float gelu_exact(float x) {
    return 0.5f * x * (1.0f + erff(x * 0.7071067811865476f));
}

// ---- Blackwell packed fp32 helpers (FFMA2 path) ----
__device__ __forceinline__ unsigned long long pack2(float lo, float hi) {
    unsigned long long r;
    asm("mov.b64 %0, {%1, %2};" : "=l"(r) : "f"(lo), "f"(hi));
    return r;
}
__device__ __forceinline__ void fma2(unsigned long long& d,
                                     unsigned long long a, unsigned long long b) {
    asm("fma.rn.f32x2 %0, %1, %2, %0;" : "+l"(d) : "l"(a), "l"(b));
}
__device__ __forceinline__ void unpack2(float& lo, float& hi, unsigned long long v) {
    asm("mov.b64 {%0, %1}, %2;" : "=f"(lo), "=f"(hi) : "l"(v));
}

// ---------------------------------------------------------------------------
// K1: ln1 + Dense(W_proj) + GELU, scatter into blocked layout
// ---------------------------------------------------------------------------
__global__ __launch_bounds__(256) void k1_ln_proj(
    const float* __restrict__ x, const float* __restrict__ ln1g,
    const float* __restrict__ ln1b, const float* __restrict__ Wp,
    const float* __restrict__ bp)
{
    __shared__ float sR[16][132];
    __shared__ float sg[128], sb[128];
    __shared__ float smean[16], srs[16];
    const int t = threadIdx.x;
    const int pbase = blockIdx.x * 16;

    if (t < 128) { sg[t] = ln1g[t]; sb[t] = ln1b[t]; }
    const float* xblk = x + (size_t)pbase * 128;
#pragma unroll
    for (int it = 0; it < 8; ++it) {
        int lin = t + it * 256;
        sR[lin >> 7][lin & 127] = xblk[lin];
    }
    __syncthreads();

    const int warp = t >> 5, lane = t & 31;
#pragma unroll
    for (int rr = 0; rr < 2; ++rr) {
        int p = warp * 2 + rr;
        float s = 0.f, s2 = 0.f;
#pragma unroll
        for (int j = 0; j < 4; ++j) {
            float v = sR[p][lane + j * 32];
            s += v; s2 += v * v;
        }
#pragma unroll
        for (int off = 16; off > 0; off >>= 1) {
            s  += __shfl_xor_sync(0xffffffffu, s,  off);
            s2 += __shfl_xor_sync(0xffffffffu, s2, off);
        }
        if (lane == 0) {
            float m = s * (1.f / 128.f);
            smean[p] = m;
            srs[p]   = rsqrtf(s2 * (1.f / 128.f) - m * m + 1e-3f);
        }
    }
    __syncthreads();
#pragma unroll
    for (int it = 0; it < 8; ++it) {
        int lin = t + it * 256;
        int p = lin >> 7, c = lin & 127;
        sR[p][c] = (sR[p][c] - smean[p]) * srs[p] * sg[c] + sb[c];
    }
    __syncthreads();

    const int f2 = t & 63;
    const int pg = t >> 6;
    float acc0[4], acc1[4];
#pragma unroll
    for (int i = 0; i < 4; ++i) { acc0[i] = 0.f; acc1[i] = 0.f; }
    const float2* Wp2 = (const float2*)Wp;
    for (int cc = 0; cc < 128; cc += 4) {
        float4 a0 = *(const float4*)&sR[pg * 4 + 0][cc];
        float4 a1 = *(const float4*)&sR[pg * 4 + 1][cc];
        float4 a2 = *(const float4*)&sR[pg * 4 + 2][cc];
        float4 a3 = *(const float4*)&sR[pg * 4 + 3][cc];
        float2 w0 = Wp2[(cc + 0) * 64 + f2];
        float2 w1 = Wp2[(cc + 1) * 64 + f2];
        float2 w2 = Wp2[(cc + 2) * 64 + f2];
        float2 w3 = Wp2[(cc + 3) * 64 + f2];
        float4 av[4] = {a0, a1, a2, a3};
#pragma unroll
        for (int i = 0; i < 4; ++i) {
            acc0[i] = fmaf(av[i].x, w0.x, acc0[i]); acc1[i] = fmaf(av[i].x, w0.y, acc1[i]);
            acc0[i] = fmaf(av[i].y, w1.x, acc0[i]); acc1[i] = fmaf(av[i].y, w1.y, acc1[i]);
            acc0[i] = fmaf(av[i].z, w2.x, acc0[i]); acc1[i] = fmaf(av[i].z, w2.y, acc1[i]);
            acc0[i] = fmaf(av[i].w, w3.x, acc0[i]); acc1[i] = fmaf(av[i].w, w3.y, acc1[i]);
        }
    }
    const float2 wb = ((const float2*)bp)[f2];
    const int branch = (f2 >= 32) ? 1 : 0;
    const int cloc = 2 * (f2 & 31);
#pragma unroll
    for (int i = 0; i < 4; ++i) {
        int p = pbase + pg * 4 + i;
        int b = p >> 16, h = (p >> 8) & 255, w = p & 255;
        int g  = ((h >> 4) << 4) | (w >> 4);
        int nn = ((h & 15) << 4) | (w & 15);
        float v0 = gelu_exact(acc0[i] + wb.x);
        float v1 = gelu_exact(acc1[i] + wb.y);
        int r = branch * 512 + (b << 8) + g;
        *(float2*)&g_bufin[(((r << 8) + nn) << 6) + cloc] = make_float2(v0, v1);
    }
}

// ---------------------------------------------------------------------------
// K2: ln2 + y = gelu(lnx @ W1[n] + b1[n]); split -> u_pre / v
// 128x128 tile, 8x8/thread via FFMA2 row-pairs, K=64 resident
// grid (3 ftiles, 8 rtiles, 256 n) x 256
// ---------------------------------------------------------------------------
__global__ __launch_bounds__(256) void k2_gmlp_in(
    const float* __restrict__ W1, const float* __restrict__ b1_,
    const float* __restrict__ ln2g, const float* __restrict__ ln2b)
{
    __shared__ float As[64][132];   // [k][row]
    __shared__ float Bs[16][132];   // [k][f]
    __shared__ float sg[64], sb[64];
    const int t = threadIdx.x;
    const int fbase = blockIdx.x * 128;
    const int rbase = blockIdx.y * 128;
    const int n = blockIdx.z;

    if (t < 64) { sg[t] = ln2g[t]; sb[t] = ln2b[t]; }

    // ---- A load + ln2 (2 threads per row) ----
    {
        const int row = t >> 1, bsel = t & 1;
        const float* src = g_bufin + ((size_t)((rbase + row) << 8) + n) * 64;
        float4 va[8];
        float s = 0.f, s2 = 0.f;
#pragma unroll
        for (int j = 0; j < 8; ++j) {
            va[j] = *(const float4*)&src[bsel * 4 + j * 8];
            s  += va[j].x + va[j].y + va[j].z + va[j].w;
            s2 += va[j].x * va[j].x + va[j].y * va[j].y
                + va[j].z * va[j].z + va[j].w * va[j].w;
        }
        s  += __shfl_xor_sync(0xffffffffu, s,  1);
        s2 += __shfl_xor_sync(0xffffffffu, s2, 1);
        float m  = s * (1.f / 64.f);
        float rs = rsqrtf(s2 * (1.f / 64.f) - m * m + 1e-3f);
        __syncthreads();  // sg/sb ready
#pragma unroll
        for (int j = 0; j < 8; ++j) {
            int k = bsel * 4 + j * 8;
            As[k + 0][row] = (va[j].x - m) * rs * sg[k + 0] + sb[k + 0];
            As[k + 1][row] = (va[j].y - m) * rs * sg[k + 1] + sb[k + 1];
            As[k + 2][row] = (va[j].z - m) * rs * sg[k + 2] + sb[k + 2];
            As[k + 3][row] = (va[j].w - m) * rs * sg[k + 3] + sb[k + 3];
        }
    }

    const int tx = t & 15, ty = t >> 4;
    const int m0 = tx * 4, r0 = ty * 4;
    unsigned long long acc2[4][8] = {};   // row-pairs x 8 f-cols

    const int bm4 = (t & 31) * 4, bk0 = t >> 5;
    const float* Wn = W1 + (size_t)n * 64 * 384 + fbase;

    for (int kb = 0; kb < 4; ++kb) {
        __syncthreads();
        *(float4*)&Bs[bk0    ][bm4] = *(const float4*)&Wn[(kb * 16 + bk0    ) * 384 + bm4];
        *(float4*)&Bs[bk0 + 8][bm4] = *(const float4*)&Wn[(kb * 16 + bk0 + 8) * 384 + bm4];
        __syncthreads();
#pragma unroll
        for (int kk = 0; kk < 16; ++kk) {
            int k = kb * 16 + kk;
            ulonglong2 a01 = *(const ulonglong2*)&As[k][r0];
            ulonglong2 a23 = *(const ulonglong2*)&As[k][r0 + 64];
            float4 b0 = *(const float4*)&Bs[kk][m0];
            float4 b1 = *(const float4*)&Bs[kk][m0 + 64];
            unsigned long long ap[4] = {a01.x, a01.y, a23.x, a23.y};
            float brr[8] = {b0.x, b0.y, b0.z, b0.w, b1.x, b1.y, b1.z, b1.w};
#pragma unroll
            for (int j = 0; j < 8; ++j) {
                unsigned long long bb = pack2(brr[j], brr[j]);
                fma2(acc2[0][j], ap[0], bb);
                fma2(acc2[1][j], ap[1], bb);
                fma2(acc2[2][j], ap[2], bb);
                fma2(acc2[3][j], ap[3], bb);
            }
        }
    }

    float accf[8][8];
#pragma unroll
    for (int ip = 0; ip < 4; ++ip)
#pragma unroll
        for (int j = 0; j < 8; ++j)
            unpack2(accf[2 * ip][j], accf[2 * ip + 1][j], acc2[ip][j]);

    // ---- epilogue: bias + gelu, route split 192 ----
#pragma unroll
    for (int jg = 0; jg < 2; ++jg) {
        int fg = fbase + m0 + jg * 64;
        float4 bias = *(const float4*)&b1_[n * 384 + fg];
        float* dst; int fo;
        if (fg < 192) { dst = g_upre; fo = fg; }
        else          { dst = g_v;    fo = fg - 192; }
#pragma unroll
        for (int i = 0; i < 8; ++i) {
            int row = rbase + (i < 4 ? r0 + i : 64 + r0 + i - 4);
            float4 o;
            o.x = gelu_exact(accf[i][jg * 4 + 0] + bias.x);
            o.y = gelu_exact(accf[i][jg * 4 + 1] + bias.y);
            o.z = gelu_exact(accf[i][jg * 4 + 2] + bias.z);
            o.w = gelu_exact(accf[i][jg * 4 + 3] + bias.w);
            *(float4*)&dst[((row << 8) + n) * 192 + fo] = o;
        }
    }
}

// ---------------------------------------------------------------------------
// K2b: ln3 over u (HF=192) + transpose -> g_ut[r][c][n]
// ---------------------------------------------------------------------------
__global__ __launch_bounds__(256) void k2b_ln3_t(
    const float* __restrict__ ln3g, const float* __restrict__ ln3b)
{
    __shared__ float s[32][193];
    __shared__ float sm[32], sr[32];
    const int t = threadIdx.x;
    const int r = blockIdx.x;
    const int nb = blockIdx.y * 32;
    const float* src = g_upre + (((size_t)r << 8) + nb) * 192;
#pragma unroll
    for (int it = 0; it < 24; ++it) {
        int lin = t + it * 256;
        s[lin / 192][lin % 192] = src[lin];
    }
    __syncthreads();
    const int warp = t >> 5, lane = t & 31;
#pragma unroll
    for (int j = 0; j < 4; ++j) {
        int row = warp * 4 + j;
        float su = 0.f, s2 = 0.f;
#pragma unroll
        for (int k = 0; k < 6; ++k) { float v = s[row][lane + k * 32]; su += v; s2 += v * v; }
#pragma unroll
        for (int off = 16; off > 0; off >>= 1) {
            su += __shfl_xor_sync(0xffffffffu, su, off);
            s2 += __shfl_xor_sync(0xffffffffu, s2, off);
        }
        if (lane == 0) {
            float m = su * (1.f / 192.f);
            sm[row] = m;
            sr[row] = rsqrtf(s2 * (1.f / 192.f) - m * m + 1e-3f);
        }
    }
    __syncthreads();
    const int n_l = t & 31, c0 = t >> 5;
#pragma unroll
    for (int it = 0; it < 24; ++it) {
        int c = c0 + it * 8;
        float v = (s[n_l][c] - sm[n_l]) * sr[n_l] * ln3g[c] + ln3b[c];
        g_ut[((r * 192 + c) << 8) + nb + n_l] = v;
    }
}

// ---------------------------------------------------------------------------
// K3: spatial gating GEMM per channel c (FFMA2 row-pairs):
//   gate[r][m] = sum_n ut[r][c][n] * Wsgu[c][n][m] + bsgu[c][m]
// 128x128 tile, BK=16; grid (2 mtiles, 8 rtiles, 192 c) x 256
// Output -> g_upre as [R][HF][N].
// ---------------------------------------------------------------------------
__global__ __launch_bounds__(256) void k3_sgu(
    const float* __restrict__ Wsgu, const float* __restrict__ bsgu)
{
    __shared__ float As[16][132];   // [k][row]
    __shared__ float Bs[16][132];   // [k][m]
    const int t = threadIdx.x;
    const int mbase = blockIdx.x * 128;
    const int rbase = blockIdx.y * 128;
    const int c = blockIdx.z;

    const int tx = t & 15, ty = t >> 4;
    const int m0 = tx * 4, r0 = ty * 4;
    unsigned long long acc2[4][8] = {};

    const int a_row = t >> 1, a_b = t & 1;
    const float* a_src = g_ut + ((size_t)(rbase + a_row) * 192 + c) * 256;
    const int bm4 = (t & 31) * 4, bk0 = t >> 5;
    const float* b_src = Wsgu + ((size_t)c << 16) + mbase;

    for (int kb = 0; kb < 256; kb += 16) {
        float4 v0 = *(const float4*)&a_src[kb + a_b * 4];
        float4 v1 = *(const float4*)&a_src[kb + a_b * 4 + 8];
        float4 w0 = *(const float4*)&b_src[(size_t)(kb + bk0    ) * 256 + bm4];
        float4 w1 = *(const float4*)&b_src[(size_t)(kb + bk0 + 8) * 256 + bm4];
        __syncthreads();
        {
            int k0 = a_b * 4;
            As[k0 + 0][a_row] = v0.x; As[k0 + 1][a_row] = v0.y;
            As[k0 + 2][a_row] = v0.z; As[k0 + 3][a_row] = v0.w;
            As[k0 + 8][a_row] = v1.x; As[k0 + 9][a_row] = v1.y;
            As[k0 +10][a_row] = v1.z; As[k0 +11][a_row] = v1.w;
            *(float4*)&Bs[bk0    ][bm4] = w0;
            *(float4*)&Bs[bk0 + 8][bm4] = w1;
        }
        __syncthreads();
#pragma unroll
        for (int k = 0; k < 16; ++k) {
            ulonglong2 a01 = *(const ulonglong2*)&As[k][r0];
            ulonglong2 a23 = *(const ulonglong2*)&As[k][r0 + 64];
            float4 b0 = *(const float4*)&Bs[k][m0];
            float4 b1 = *(const float4*)&Bs[k][m0 + 64];
            unsigned long long ap[4] = {a01.x, a01.y, a23.x, a23.y};
            float brr[8] = {b0.x, b0.y, b0.z, b0.w, b1.x, b1.y, b1.z, b1.w};
#pragma unroll
            for (int j = 0; j < 8; ++j) {
                unsigned long long bb = pack2(brr[j], brr[j]);
                fma2(acc2[0][j], ap[0], bb);
                fma2(acc2[1][j], ap[1], bb);
                fma2(acc2[2][j], ap[2], bb);
                fma2(acc2[3][j], ap[3], bb);
            }
        }
    }

    float accf[8][8];
#pragma unroll
    for (int ip = 0; ip < 4; ++ip)
#pragma unroll
        for (int j = 0; j < 8; ++j)
            unpack2(accf[2 * ip][j], accf[2 * ip + 1][j], acc2[ip][j]);

    float4 bg0 = *(const float4*)&bsgu[(c << 8) + mbase + m0];
    float4 bg1 = *(const float4*)&bsgu[(c << 8) + mbase + m0 + 64];
#pragma unroll
    for (int i = 0; i < 8; ++i) {
        int row = rbase + (i < 4 ? r0 + i : 64 + r0 + i - 4);
        float* dst = &g_upre[((size_t)(row * 192 + c) << 8) + mbase];
        *(float4*)&dst[m0] = make_float4(accf[i][0] + bg0.x, accf[i][1] + bg0.y,
                                         accf[i][2] + bg0.z, accf[i][3] + bg0.w);
        *(float4*)&dst[m0 + 64] = make_float4(accf[i][4] + bg1.x, accf[i][5] + bg1.y,
                                              accf[i][6] + bg1.z, accf[i][7] + bg1.w);
    }
}

// ---------------------------------------------------------------------------
// K3b: uv[r][n][c] = gate[r][c][n] * v[r][n][c]
// ---------------------------------------------------------------------------
__global__ __launch_bounds__(256) void k3b_gate_mul()
{
    __shared__ float s[32][33];
    const int t = threadIdx.x;
    const int r = blockIdx.x;
    const int nb = blockIdx.y * 32;
    const int cb = blockIdx.z * 32;
    {
        int n_l = t & 31, c0 = t >> 5;
#pragma unroll
        for (int it = 0; it < 4; ++it) {
            int cc = c0 + it * 8;
            s[cc][n_l] = g_upre[((r * 192 + cb + cc) << 8) + nb + n_l];
        }
    }
    __syncthreads();
    {
        int c_l = t & 31, n0 = t >> 5;
#pragma unroll
        for (int it = 0; it < 4; ++it) {
            int nn = n0 + it * 8;
            int idx = (((r << 8) + nb + nn) * 192) + cb + c_l;
            g_ut[idx] = s[c_l][nn] * g_v[idx];
        }
    }
}

// ---------------------------------------------------------------------------
// K4: z = uv @ W2[n] + b2[n] + bufin  (FFMA2 row-pairs)
// 128x64 tile, BK=16; grid (8 rtiles, 256 n) x 256
// ---------------------------------------------------------------------------
__global__ __launch_bounds__(256) void k4_gmlp_out(
    const float* __restrict__ W2, const float* __restrict__ b2_)
{
    __shared__ float As[16][132];
    __shared__ float Bs[16][68];
    const int t = threadIdx.x;
    const int rbase = blockIdx.x * 128;
    const int n = blockIdx.y;

    const int tx = t & 15, ty = t >> 4;
    const int f0 = tx * 4, r0 = ty * 4;
    unsigned long long acc2[4][4] = {};

    const int a_row = t >> 1, a_b = t & 1;
    const float* a_src = g_ut + ((size_t)((rbase + a_row) << 8) + n) * 192;
    const int bf4 = (t & 15) * 4, bk = t >> 4;
    const float* b_src = W2 + (size_t)n * 192 * 64;

    for (int kb = 0; kb < 192; kb += 16) {
        float4 v0 = *(const float4*)&a_src[kb + a_b * 4];
        float4 v1 = *(const float4*)&a_src[kb + a_b * 4 + 8];
        float4 w0 = *(const float4*)&b_src[(kb + bk) * 64 + bf4];
        __syncthreads();
        {
            int k0 = a_b * 4;
            As[k0 + 0][a_row] = v0.x; As[k0 + 1][a_row] = v0.y;
            As[k0 + 2][a_row] = v0.z; As[k0 + 3][a_row] = v0.w;
            As[k0 + 8][a_row] = v1.x; As[k0 + 9][a_row] = v1.y;
            As[k0 +10][a_row] = v1.z; As[k0 +11][a_row] = v1.w;
            *(float4*)&Bs[bk][bf4] = w0;
        }
        __syncthreads();
#pragma unroll
        for (int k = 0; k < 16; ++k) {
            ulonglong2 a01 = *(const ulonglong2*)&As[k][r0];
            ulonglong2 a23 = *(const ulonglong2*)&As[k][r0 + 64];
            float4 b0 = *(const float4*)&Bs[k][f0];
            unsigned long long ap[4] = {a01.x, a01.y, a23.x, a23.y};
            float brr[4] = {b0.x, b0.y, b0.z, b0.w};
#pragma unroll
            for (int j = 0; j < 4; ++j) {
                unsigned long long bb = pack2(brr[j], brr[j]);
                fma2(acc2[0][j], ap[0], bb);
                fma2(acc2[1][j], ap[1], bb);
                fma2(acc2[2][j], ap[2], bb);
                fma2(acc2[3][j], ap[3], bb);
            }
        }
    }

    float accf[8][4];
#pragma unroll
    for (int ip = 0; ip < 4; ++ip)
#pragma unroll
        for (int j = 0; j < 4; ++j)
            unpack2(accf[2 * ip][j], accf[2 * ip + 1][j], acc2[ip][j]);

    float4 bias = *(const float4*)&b2_[(n << 6) + f0];
#pragma unroll
    for (int i = 0; i < 8; ++i) {
        int row = rbase + (i < 4 ? r0 + i : 64 + r0 + i - 4);
        int idx = (((row << 8) + n) << 6) + f0;
        float4 xin = *(const float4*)&g_bufin[idx];
        *(float4*)&g_z[idx] = make_float4(accf[i][0] + bias.x + xin.x,
                                          accf[i][1] + bias.y + xin.y,
                                          accf[i][2] + bias.z + xin.z,
                                          accf[i][3] + bias.w + xin.w);
    }
}

// ---------------------------------------------------------------------------
// K5: recon + concat + outer residual; glob out
// ---------------------------------------------------------------------------
__global__ __launch_bounds__(256) void k5_assemble(
    const float* __restrict__ x, float* __restrict__ out,
    float* __restrict__ gout, int write_glob)
{
    const int t = threadIdx.x;
    const int pix = blockIdx.x * 16 + (t >> 4);
    const int c = (t & 15) * 4;
    const int b = pix >> 16, h = (pix >> 8) & 255, w = pix & 255;
    const int gb  = ((h >> 4) << 4) | (w >> 4);
    const int nb2 = ((h & 15) << 4) | (w & 15);
    const int rl = (b << 8) + nb2;
    const int rg = 512 + (b << 8) + gb;
    float4 zl = *(const float4*)&g_z[(((rl << 8) + gb)  << 6) + c];
    float4 zg = *(const float4*)&g_z[(((rg << 8) + nb2) << 6) + c];
    float4 xa = *(const float4*)&x[pix * 128 + c];
    float4 xb = *(const float4*)&x[pix * 128 + 64 + c];
    *(float4*)&out[pix * 128 + c] =
        make_float4(zl.x + xa.x, zl.y + xa.y, zl.z + xa.z, zl.w + xa.w);
    *(float4*)&out[pix * 128 + 64 + c] =
        make_float4(zg.x + xb.x, zg.y + xb.y, zg.z + xb.z, zg.w + xb.w);
    if (write_glob)
        *(float4*)&gout[pix * 64 + c] = zg;
}

// ---------------------------------------------------------------------------
extern "C" void kernel_launch(void* const* d_in, const int* in_sizes, int n_in,
                              void* d_out, int out_size)
{
    const float* x    = (const float*)d_in[0];
    const float* ln1g = (const float*)d_in[1];
    const float* ln1b = (const float*)d_in[2];
    const float* Wp   = (const float*)d_in[3];
    const float* bp   = (const float*)d_in[4];
    const float* ln2g = (const float*)d_in[5];
    const float* ln2b = (const float*)d_in[6];
    const float* W1   = (const float*)d_in[7];
    const float* b1   = (const float*)d_in[8];
    const float* ln3g = (const float*)d_in[9];
    const float* ln3b = (const float*)d_in[10];
    const float* Wsgu = (const float*)d_in[11];
    const float* bsgu = (const float*)d_in[12];
    const float* W2   = (const float*)d_in[13];
    const float* b2   = (const float*)d_in[14];

    float* out = (float*)d_out;
    const int OUT_MAIN = 2 * 256 * 256 * 128;
    const int OUT_GLOB = 2 * 256 * 256 * 64;
    int write_glob = (out_size >= OUT_MAIN + OUT_GLOB) ? 1 : 0;
    float* gout = out + OUT_MAIN;

    k1_ln_proj   <<<8192, 256>>>(x, ln1g, ln1b, Wp, bp);
    k2_gmlp_in   <<<dim3(3, 8, 256), 256>>>(W1, b1, ln2g, ln2b);
    k2b_ln3_t    <<<dim3(1024, 8, 1), 256>>>(ln3g, ln3b);
    k3_sgu       <<<dim3(2, 8, 192), 256>>>(Wsgu, bsgu);
    k3b_gate_mul <<<dim3(1024, 8, 6), 256>>>();
    k4_gmlp_out  <<<dim3(8, 256, 1), 256>>>(W2, b2);
    k5_assemble  <<<8192, 256>>>(x, out, gout, write_glob);
}